// round 4
// baseline (speedup 1.0000x reference)
#include <cuda_runtime.h>
#include <math_constants.h>

#define QT      4
#define TK      1024
#define TQ      1024
#define D       64
#define THREADS 256

__device__ __forceinline__ float fast_tanh(float x) {
    float y;
    asm("tanh.approx.f32 %0, %1;" : "=f"(y) : "f"(x));
    return y;
}

// 64 regs -> 4 CTAs/SM; grid=512 -> whole grid resident in one wave
__global__ __launch_bounds__(THREADS, 4)
void addattn_kernel(const float* __restrict__ q,
                    const float* __restrict__ v,
                    const float* __restrict__ scale,
                    float* __restrict__ out)
{
    __shared__ float qs[QT][D];          // 1 KB   q tile
    __shared__ float ss[D];              // 256 B  scale
    __shared__ float sc[QT][TK];         // 16 KB  scores -> probs
    __shared__ float rsum[QT];           //        1/sum per q row
    __shared__ float pmax[2][QT];        //        softmax half-maxima
    __shared__ float psum[2][QT];        //        softmax half-sums
    __shared__ float part[4][QT][D];     // 4 KB   pass-2 partials

    const int tid = threadIdx.x;
    const int b  = blockIdx.x >> 8;              // 256 q-blocks per batch
    const int q0 = (blockIdx.x & 255) * QT;

    const float* qbase = q + ((size_t)b * TQ + q0) * D;
    const float* vbase = v + (size_t)b * TK * D;

    // ---- stage q tile + scale into smem ----
    if (tid < QT * D) qs[tid / D][tid % D] = qbase[tid];
    if (tid < D) ss[tid] = scale[tid];
    __syncthreads();

    // ---- pass 1: scores[q][k] = sum_d scale[d]*tanh(q[q][d] + v[k][d]) ----
    const float4* s4 = (const float4*)ss;
    #pragma unroll 1
    for (int kk = 0; kk < TK / THREADS; kk++) {
        const int k = kk * THREADS + tid;
        const float4* vrow = (const float4*)(vbase + (size_t)k * D);

        float acc[QT];
        #pragma unroll
        for (int qi = 0; qi < QT; qi++) acc[qi] = 0.f;

        #pragma unroll 4
        for (int d4 = 0; d4 < D / 4; d4++) {
            const float4 vv = vrow[d4];   // L1/L2-resident
            const float4 sv = s4[d4];     // smem broadcast
            #pragma unroll
            for (int qi = 0; qi < QT; qi++) {
                const float4 qq = ((const float4*)qs[qi])[d4];  // smem broadcast
                float a = acc[qi];
                a += sv.x * fast_tanh(qq.x + vv.x);
                a += sv.y * fast_tanh(qq.y + vv.y);
                a += sv.z * fast_tanh(qq.z + vv.z);
                a += sv.w * fast_tanh(qq.w + vv.w);
                acc[qi] = a;
            }
        }
        #pragma unroll
        for (int qi = 0; qi < QT; qi++) sc[qi][k] = acc[qi];
    }
    __syncthreads();

    // ---- softmax: row r handled by warps r and r+4 (split-k halves) ----
    const int wid  = tid >> 5;
    const int lane = tid & 31;
    const int row  = wid & 3;
    const int half = wid >> 2;
    {
        float m = -CUDART_INF_F;
        #pragma unroll 4
        for (int k = half * 32 + lane; k < TK; k += 64) m = fmaxf(m, sc[row][k]);
        #pragma unroll
        for (int o = 16; o; o >>= 1) m = fmaxf(m, __shfl_xor_sync(0xffffffffu, m, o));
        if (lane == 0) pmax[half][row] = m;
        __syncthreads();
        const float M = fmaxf(pmax[0][row], pmax[1][row]);

        float s = 0.f;
        #pragma unroll 4
        for (int k = half * 32 + lane; k < TK; k += 64) {
            float p = __expf(sc[row][k] - M);   // MUFU.EX2
            sc[row][k] = p;
            s += p;
        }
        #pragma unroll
        for (int o = 16; o; o >>= 1) s += __shfl_xor_sync(0xffffffffu, s, o);
        if (lane == 0) psum[half][row] = s;
        __syncthreads();
        if (tid < QT) rsum[tid] = 1.f / (psum[0][tid] + psum[1][tid]);
    }
    __syncthreads();

    // ---- pass 2: out[q][d] = (1/sum) * sum_k p[q][k] * v[k][d] ----
    // group g owns contiguous k block [g*256, (g+1)*256); float4 prob loads.
    const int d = tid & 63;
    const int g = tid >> 6;
    const int kbase = g * (TK / 4);
    float acc[QT];
    #pragma unroll
    for (int qi = 0; qi < QT; qi++) acc[qi] = 0.f;

    #pragma unroll 2
    for (int kq = 0; kq < TK / 16; kq++) {       // 64 iters of 4 k each
        const int k = kbase + kq * 4;
        const float* vp = vbase + (size_t)k * D + d;
        float v0 = vp[0];          // coalesced LDG.32 per warp
        float v1 = vp[D];
        float v2 = vp[2 * D];
        float v3 = vp[3 * D];
        #pragma unroll
        for (int qi = 0; qi < QT; qi++) {
            float4 p = ((const float4*)sc[qi])[(kbase >> 2) + kq];  // LDS.128 broadcast
            acc[qi] += p.x * v0 + p.y * v1 + p.z * v2 + p.w * v3;
        }
    }
    #pragma unroll
    for (int qi = 0; qi < QT; qi++) part[g][qi][d] = acc[qi];
    __syncthreads();

    // cross-group reduce: thread (g,d) finalizes row g
    {
        const int qi = g;
        float r = part[0][qi][d] + part[1][qi][d] + part[2][qi][d] + part[3][qi][d];
        out[((size_t)b * TQ + q0 + qi) * D + d] = r * rsum[qi];
    }
}

extern "C" void kernel_launch(void* const* d_in, const int* in_sizes, int n_in,
                              void* d_out, int out_size)
{
    const float* query = (const float*)d_in[0];
    const float* value = (const float*)d_in[1];
    const float* scale = (const float*)d_in[2];
    float* out = (float*)d_out;

    dim3 grid(2 * TQ / QT);   // 512 blocks
    dim3 block(THREADS);
    addattn_kernel<<<grid, block>>>(query, value, scale, out);
}

// round 7
// speedup vs baseline: 1.1929x; 1.1929x over previous
#include <cuda_runtime.h>
#include <math_constants.h>

#define QT      4
#define TK      1024
#define TQ      1024
#define D       64
#define THREADS 256

__device__ __forceinline__ float fast_tanh(float x) {
    float y;
    asm("tanh.approx.f32 %0, %1;" : "=f"(y) : "f"(x));
    return y;
}

__global__ __launch_bounds__(THREADS, 4)
void addattn_kernel(const float* __restrict__ q,
                    const float* __restrict__ v,
                    const float* __restrict__ scale,
                    float* __restrict__ out)
{
    __shared__ float sc[QT][TK];         // 16 KB  scores -> probs
    __shared__ float rsum[QT];           //        1/sum per q row
    __shared__ float pmax[2][QT];        //        softmax half-maxima
    __shared__ float psum[2][QT];        //        softmax half-sums
    __shared__ float part[4][QT][D];     // 4 KB   pass-2 partials

    const int tid = threadIdx.x;
    const int b  = blockIdx.x >> 8;              // 256 q-blocks per batch
    const int q0 = (blockIdx.x & 255) * QT;

    const float* qbase = q + ((size_t)b * TQ + q0) * D;
    const float* vbase = v + (size_t)b * TK * D;

    const int wid  = tid >> 5;
    const int lane = tid & 31;

    // ---- pass 1: lanes = (kr, dc): kr=k-row within 4-row group, dc=8-float d-chunk ----
    {
        const int kr = lane >> 3;       // 0..3
        const int dc = lane & 7;        // 0..7  -> owns d in [dc*8, dc*8+8)

        // q slices + scale slice in registers (loaded once, gmem tiny)
        float qreg[QT][8];
        float sreg[8];
        {
            const float4* sp = (const float4*)(scale + dc * 8);
            float4 sa = sp[0], sb = sp[1];
            sreg[0]=sa.x; sreg[1]=sa.y; sreg[2]=sa.z; sreg[3]=sa.w;
            sreg[4]=sb.x; sreg[5]=sb.y; sreg[6]=sb.z; sreg[7]=sb.w;
            #pragma unroll
            for (int qi = 0; qi < QT; qi++) {
                const float4* qp = (const float4*)(qbase + qi * D + dc * 8);
                float4 qa = qp[0], qb = qp[1];
                qreg[qi][0]=qa.x; qreg[qi][1]=qa.y; qreg[qi][2]=qa.z; qreg[qi][3]=qa.w;
                qreg[qi][4]=qb.x; qreg[qi][5]=qb.y; qreg[qi][6]=qb.z; qreg[qi][7]=qb.w;
            }
        }

        // warp owns k in [wid*128, wid*128+128), 4 rows per iteration
        const int kw = wid * 128;
        #pragma unroll 1
        for (int it = 0; it < 32; it++) {
            const int k = kw + it * 4 + kr;
            // coalesced: 8 dc-lanes cover one 256B V row
            const float4* vp = (const float4*)(vbase + (size_t)k * D + dc * 8);
            const float4 va = vp[0], vb = vp[1];
            float vv[8];
            vv[0]=va.x; vv[1]=va.y; vv[2]=va.z; vv[3]=va.w;
            vv[4]=vb.x; vv[5]=vb.y; vv[6]=vb.z; vv[7]=vb.w;

            #pragma unroll
            for (int qi = 0; qi < QT; qi++) {
                float a = 0.f;
                #pragma unroll
                for (int j = 0; j < 8; j++)
                    a = fmaf(sreg[j], fast_tanh(qreg[qi][j] + vv[j]), a);
                // reduce over the 8 dc-lanes (low 3 bits of lane)
                a += __shfl_xor_sync(0xffffffffu, a, 1);
                a += __shfl_xor_sync(0xffffffffu, a, 2);
                a += __shfl_xor_sync(0xffffffffu, a, 4);
                if (dc == 0) sc[qi][k] = a;
            }
        }
    }
    __syncthreads();

    // ---- softmax: row r handled by warps r and r+4 (split-k halves) ----
    {
        const int row  = wid & 3;
        const int half = wid >> 2;
        float m = -CUDART_INF_F;
        #pragma unroll 4
        for (int k = half * 32 + lane; k < TK; k += 64) m = fmaxf(m, sc[row][k]);
        #pragma unroll
        for (int o = 16; o; o >>= 1) m = fmaxf(m, __shfl_xor_sync(0xffffffffu, m, o));
        if (lane == 0) pmax[half][row] = m;
        __syncthreads();
        const float M = fmaxf(pmax[0][row], pmax[1][row]);

        float s = 0.f;
        #pragma unroll 4
        for (int k = half * 32 + lane; k < TK; k += 64) {
            float p = __expf(sc[row][k] - M);   // MUFU.EX2
            sc[row][k] = p;
            s += p;
        }
        #pragma unroll
        for (int o = 16; o; o >>= 1) s += __shfl_xor_sync(0xffffffffu, s, o);
        if (lane == 0) psum[half][row] = s;
        __syncthreads();
        if (tid < QT) rsum[tid] = 1.f / (psum[0][tid] + psum[1][tid]);
    }
    __syncthreads();

    // ---- pass 2: out[q][d] = (1/sum) * sum_k p[q][k] * v[k][d] ----
    const int d = tid & 63;
    const int g = tid >> 6;
    const int kbase = g * (TK / 4);
    float acc[QT];
    #pragma unroll
    for (int qi = 0; qi < QT; qi++) acc[qi] = 0.f;

    #pragma unroll 2
    for (int kq = 0; kq < TK / 16; kq++) {       // 64 iters of 4 k each
        const int k = kbase + kq * 4;
        const float* vp = vbase + (size_t)k * D + d;
        float v0 = vp[0];          // coalesced per warp
        float v1 = vp[D];
        float v2 = vp[2 * D];
        float v3 = vp[3 * D];
        #pragma unroll
        for (int qi = 0; qi < QT; qi++) {
            float4 p = ((const float4*)sc[qi])[(kbase >> 2) + kq];  // LDS.128 broadcast
            acc[qi] += p.x * v0 + p.y * v1 + p.z * v2 + p.w * v3;
        }
    }
    #pragma unroll
    for (int qi = 0; qi < QT; qi++) part[g][qi][d] = acc[qi];
    __syncthreads();

    // cross-group reduce: thread (g,d) finalizes row g
    {
        const int qi = g;
        float r = part[0][qi][d] + part[1][qi][d] + part[2][qi][d] + part[3][qi][d];
        out[((size_t)b * TQ + q0 + qi) * D + d] = r * rsum[qi];
    }
}

extern "C" void kernel_launch(void* const* d_in, const int* in_sizes, int n_in,
                              void* d_out, int out_size)
{
    const float* query = (const float*)d_in[0];
    const float* value = (const float*)d_in[1];
    const float* scale = (const float*)d_in[2];
    float* out = (float*)d_out;

    dim3 grid(2 * TQ / QT);   // 512 blocks
    dim3 block(THREADS);
    addattn_kernel<<<grid, block>>>(query, value, scale, out);
}